// round 12
// baseline (speedup 1.0000x reference)
#include <cuda_runtime.h>
#include <cuda_bf16.h>
#include <math.h>

// Problem shapes (fixed by the dataset)
#define BDIM 8
#define NDIM 8192
#define CDIM 256
#define HDIM 256
#define ODIM 256
#define KDIM 64
#define KCHUNK 4
#define NCHUNKS (KDIM / KCHUNK)   // 16
#define NCOMPUTE (NCHUNKS * BDIM) // 128 compute blocks
#define NGEMV 8                   // gemv blocks (o-tiles of 32)
#define CONC (CDIM + HDIM)        // 512
#define CS_PAD 516                // padded concat row (conflict-free bb-split)
#define NTILE 16                  // c-tiles of 16 (16 c x 256 h = 16KB each)
#define LEAKY_ALPHA 0.3f
#define EPS 1e-6f

// Global scratch / sync (no allocation)
__device__ float g_partial[BDIM * NCHUNKS * HDIM];  // per-(b,chunk) weighted hidden sums
__device__ float g_wsum[BDIM * NCHUNKS];            // per-(b,chunk) neighbor-weight sums
__device__ float g_hidden[BDIM * ODIM];             // pre-norm hidden
__device__ float g_ssq[BDIM * NGEMV];               // per-(b, o-block) sum of squares
__device__ int   g_done   = 0;                      // compute completion counter
__device__ int   g_arrive = 0;                      // gemv arrival counter

__device__ __forceinline__ float leaky(float x) {
    return x >= 0.0f ? x : LEAKY_ALPHA * x;
}

__global__ void __launch_bounds__(1024, 1)
fused_convolve(const float* __restrict__ emb,
               const float* __restrict__ weights,
               const float* __restrict__ Qw,
               const float* __restrict__ Qb,
               const float* __restrict__ Ww,
               const float* __restrict__ Wb,
               const int*   __restrict__ nb,
               const int*   __restrict__ nid_p,
               float*       __restrict__ out)
{
    // Shared memory, carved per role (compute: 36.9 KB; gemv: 33.2 KB).
    __shared__ __align__(16) unsigned char smem_raw[37376];
    __shared__ float s_misc[12];

    const int bid = blockIdx.x;
    const int tid = threadIdx.x;
    const int nid = *nid_p;

    if (bid < NCOMPUTE) {
        // ============== COMPUTE ROLE: smem-staged, double-buffered Qw ==============
        // block = (chunk of 4 neighbors, batch b).
        // thread = (th: h-group of 4) x (tk: neighbor) x (tcs: c-split of 4 within tile)
        const int chunk = bid >> 3;     // 0..15
        const int b     = bid & 7;      // 0..7
        const int th    = tid & 63;     // h-group (float4 column of Qw)
        const int tk    = (tid >> 6) & 3;  // neighbor 0..3
        const int tcs   = tid >> 8;     // c-split 0..3

        float4* qbuf0 = (float4*)smem_raw;              // [1024] = 16 KB (tile even)
        float4* qbuf1 = (float4*)(smem_raw + 16384);    // [1024] = 16 KB (tile odd)
        float*  embs  = (float*)(smem_raw + 32768);     // [4][256] = 4 KB
        float*  ws    = (float*)(smem_raw + 36864);     // [4]
        int*    nbs   = (int*)  (smem_raw + 36880);     // [4]

        const float4* Qw4 = (const float4*)Qw;   // (256 c) x (64 float4 of h)

        // Stage tile 0 + prefetch tile 1 (linear, fully coalesced, independent)
        float4 qa    = __ldg(&Qw4[tid]);
        float4 qnext = __ldg(&Qw4[1024 + tid]);

        if (tid < KCHUNK) {
            int n = nb[chunk * KCHUNK + tid];
            nbs[tid] = n;
            ws[tid] = weights[(size_t)n * NDIM + nid];
        }
        qbuf0[tid] = qa;
        __syncthreads();   // nbs + tile0 visible

        if (tid < 256) {
            int r = tid >> 6, col = tid & 63;
            ((float4*)(embs + r * CDIM))[col] =
                ((const float4*)(emb + ((size_t)b * NDIM + nbs[r]) * CDIM))[col];
        }
        __syncthreads();   // embs visible

        const float* er = embs + tk * CDIM;
        float4 acc = make_float4(0.f, 0.f, 0.f, 0.f);

        // Main pipeline: one barrier per tile.
        //  iter t: STS tile t+1 (into the buffer last read at t-1, safe past the
        //  t-1 barrier); LDG tile t+2 into regs; compute tile t; barrier.
        #pragma unroll
        for (int t = 0; t < NTILE; t++) {
            float4* buf  = (t & 1) ? qbuf1 : qbuf0;
            float4* nbuf = (t & 1) ? qbuf0 : qbuf1;
            if (t < NTILE - 1) nbuf[tid] = qnext;
            if (t < NTILE - 2) qnext = __ldg(&Qw4[(t + 2) * 1024 + tid]);

            #pragma unroll
            for (int i = 0; i < 4; i++) {
                const int cl = tcs * 4 + i;          // c within tile
                float  e = er[t * 16 + cl];          // broadcast LDS
                float4 q = buf[cl * 64 + th];        // conflict-free LDS.128
                acc.x = fmaf(e, q.x, acc.x);
                acc.y = fmaf(e, q.y, acc.y);
                acc.z = fmaf(e, q.z, acc.z);
                acc.w = fmaf(e, q.w, acc.w);
            }
            __syncthreads();
        }

        // c-split combine: part[tcs][tk][th] overlays qbuf0 (1024 float4 = 16 KB).
        float4* part = qbuf0;
        part[tid] = acc;     // index = tcs*256 + tk*64 + th == tid
        __syncthreads();

        if (tid < 256) {
            const int k = tid >> 6, h = tid & 63;
            float4 s = part[k * 64 + h];
            #pragma unroll
            for (int j = 1; j < 4; j++) {
                float4 p = part[j * 256 + k * 64 + h];
                s.x += p.x; s.y += p.y; s.z += p.z; s.w += p.w;
            }
            float4 qb = ((const float4*)Qb)[h];
            float  w  = ws[k];
            float4 r;
            r.x = leaky(s.x + qb.x) * w;
            r.y = leaky(s.y + qb.y) * w;
            r.z = leaky(s.z + qb.z) * w;
            r.w = leaky(s.w + qb.w) * w;
            part[k * 64 + h] = r;
        }
        __syncthreads();

        if (tid < 64) {
            float4 s0 = part[0 * 64 + tid], s1 = part[1 * 64 + tid];
            float4 s2 = part[2 * 64 + tid], s3 = part[3 * 64 + tid];
            float4 s;
            s.x = s0.x + s1.x + s2.x + s3.x;
            s.y = s0.y + s1.y + s2.y + s3.y;
            s.z = s0.z + s1.z + s2.z + s3.z;
            s.w = s0.w + s1.w + s2.w + s3.w;
            ((float4*)(g_partial + ((size_t)b * NCHUNKS + chunk) * HDIM))[tid] = s;
        }
        if (tid == 0) {
            g_wsum[b * NCHUNKS + chunk] = ws[0] + ws[1] + ws[2] + ws[3];
        }
        __threadfence();
        __syncthreads();
        if (tid == 0) atomicAdd(&g_done, 1);

    } else {
        // ================= GEMV ROLE (proven R10 body) =================
        const int ob = bid - NCOMPUTE;   // 0..7, o-tile of 32

        float*  cs_s = (float*)smem_raw;                       // [8][CS_PAD] = 16.5 KB
        float4* red  = (float4*)(smem_raw + 8 * CS_PAD * 4);   // [16][64]    = 16 KB
        float*  sq   = (float*)(smem_raw + 8 * CS_PAD * 4 + 16384);  // [64]
        float*  dn   = (float*)(smem_raw + 8 * CS_PAD * 4 + 16640);  // [8]
        int*    s_fl = (int*)  (smem_raw + 8 * CS_PAD * 4 + 16672);

        // Pre-gate: node embeddings (independent of compute blocks) -> overlap
        if (tid < 512) {
            int bn = tid >> 6, col = tid & 63;
            float4 v = *(const float4*)(emb + ((size_t)(bn * NDIM + nid)) * CDIM + col * 4);
            *(float4*)(cs_s + bn * CS_PAD + col * 4) = v;
        }

        // Gate on compute completion
        if (tid == 0) {
            while (atomicAdd(&g_done, 0) < NCOMPUTE) __nanosleep(64);
        }
        __syncthreads();
        __threadfence();

        // Phase A remainder: reduce 16 chunk partials + denoms (cross-SM -> __ldcg)
        float s0 = 0.f, s1 = 0.f;
        {
            const int b0 = tid >> 8, h0 = tid & 255;
            const int b1 = b0 + 4;
            const float* gp0 = g_partial + ((size_t)b0 * NCHUNKS) * HDIM + h0;
            const float* gp1 = g_partial + ((size_t)b1 * NCHUNKS) * HDIM + h0;
            #pragma unroll
            for (int ch = 0; ch < NCHUNKS; ch++) {
                s0 += __ldcg(gp0 + ch * HDIM);
                s1 += __ldcg(gp1 + ch * HDIM);
            }
        }
        if (tid >= 512 && tid < 512 + BDIM) {
            const int bn = tid - 512;
            float d = 0.0f;
            #pragma unroll
            for (int i = 0; i < NCHUNKS; i++) d += __ldcg(&g_wsum[bn * NCHUNKS + i]);
            dn[bn] = d + EPS;
        }
        __syncthreads();
        {
            const int b0 = tid >> 8, h0 = tid & 255;
            const int b1 = b0 + 4;
            cs_s[b0 * CS_PAD + CDIM + h0] = s0 / dn[b0];
            cs_s[b1 * CS_PAD + CDIM + h0] = s1 / dn[b1];
        }
        __syncthreads();

        // Phase B: GEMV — o-tile for all 8 batches
        const int og = tid & 7;
        const int bb = (tid >> 3) & 7;
        const int cq = tid >> 6;
        const float4* Ww4 = (const float4*)Ww;
        const float*  e   = cs_s + bb * CS_PAD;

        float4 acc = make_float4(0.f,0.f,0.f,0.f);
        #pragma unroll 8
        for (int c = cq * 32; c < cq * 32 + 32; c++) {
            float  ev = e[c];
            float4 q  = __ldg(&Ww4[c * 64 + ob * 8 + og]);
            acc.x = fmaf(ev, q.x, acc.x);
            acc.y = fmaf(ev, q.y, acc.y);
            acc.z = fmaf(ev, q.z, acc.z);
            acc.w = fmaf(ev, q.w, acc.w);
        }
        red[cq * 64 + bb * 8 + og] = acc;
        __syncthreads();

        if (tid < 64) {
            const int b2 = tid >> 3, og2 = tid & 7;
            float4 s = red[tid];
            #pragma unroll
            for (int i = 1; i < 16; i++) {
                float4 rr = red[i * 64 + tid];
                s.x += rr.x; s.y += rr.y; s.z += rr.z; s.w += rr.w;
            }
            float4 wb = ((const float4*)Wb)[ob * 8 + og2];
            float4 v;
            v.x = leaky(s.x + wb.x);
            v.y = leaky(s.y + wb.y);
            v.z = leaky(s.z + wb.z);
            v.w = leaky(s.w + wb.w);
            *(float4*)(g_hidden + (size_t)b2 * ODIM + ob * 32 + og2 * 4) = v;
            sq[tid] = v.x*v.x + v.y*v.y + v.z*v.z + v.w*v.w;
        }
        __syncthreads();
        if (tid < 8) {
            float t = 0.f;
            #pragma unroll
            for (int i = 0; i < 8; i++) t += sq[tid * 8 + i];
            g_ssq[tid * NGEMV + ob] = t;
        }
        __threadfence();
        __syncthreads();
        if (tid == 0) *s_fl = (atomicAdd(&g_arrive, 1) == NGEMV - 1);
        __syncthreads();

        if (*s_fl) {
            // Last-arriving gemv block: normalize + store + reset counters.
            __threadfence();
            if (tid < 8) {
                float t = 0.f;
                #pragma unroll
                for (int i = 0; i < 8; i++) t += __ldcg(&g_ssq[tid * NGEMV + i]);
                s_misc[tid] = 1.0f / (sqrtf(t) + EPS);
            }
            __syncthreads();
            if (tid < 512) {
                int bn = tid >> 6, o4 = tid & 63;
                float4 v = __ldcg(((const float4*)(g_hidden + (size_t)bn * ODIM)) + o4);
                float iv = s_misc[bn];
                v.x *= iv; v.y *= iv; v.z *= iv; v.w *= iv;
                *(float4*)(out + (size_t)bn * ODIM + o4 * 4) = v;
            }
            if (tid == 0) { g_done = 0; g_arrive = 0; }
        }
    }
}

extern "C" void kernel_launch(void* const* d_in, const int* in_sizes, int n_in,
                              void* d_out, int out_size)
{
    (void)in_sizes; (void)n_in; (void)out_size;
    const float* emb     = (const float*)d_in[0];
    const float* weights = (const float*)d_in[1];
    const float* Qw      = (const float*)d_in[2];
    const float* Qb      = (const float*)d_in[3];
    const float* Ww      = (const float*)d_in[4];
    const float* Wb      = (const float*)d_in[5];
    const int*   nb      = (const int*)d_in[6];
    const int*   nid     = (const int*)d_in[7];
    float*       out     = (float*)d_out;

    fused_convolve<<<NCOMPUTE + NGEMV, 1024>>>(emb, weights, Qw, Qb, Ww, Wb, nb, nid, out);
}

// round 13
// speedup vs baseline: 1.2444x; 1.2444x over previous
#include <cuda_runtime.h>
#include <cuda_bf16.h>
#include <math.h>

// Problem shapes (fixed by the dataset)
#define BDIM 8
#define NDIM 8192
#define CDIM 256
#define HDIM 256
#define ODIM 256
#define KDIM 64
#define KCHUNK 4
#define NCHUNKS (KDIM / KCHUNK)   // 16
#define NCOMPUTE (NCHUNKS * BDIM) // 128 compute blocks
#define NGEMV 8                   // gemv blocks (o-tiles of 32)
#define CONC (CDIM + HDIM)        // 512
#define CS_PAD 516                // padded concat row (conflict-free bb-split)
#define LEAKY_ALPHA 0.3f
#define EPS 1e-6f

// Global scratch / sync (no allocation)
__device__ float g_partial[BDIM * NCHUNKS * HDIM];  // per-(b,chunk) weighted hidden sums
__device__ float g_wsum[BDIM * NCHUNKS];            // per-(b,chunk) neighbor-weight sums
__device__ float g_hidden[BDIM * ODIM];             // pre-norm hidden
__device__ float g_ssq[BDIM * NGEMV];               // per-(b, o-block) sum of squares
__device__ int   g_done   = 0;                      // compute completion counter
__device__ int   g_arrive = 0;                      // gemv arrival counter

__device__ __forceinline__ float leaky(float x) {
    return x >= 0.0f ? x : LEAKY_ALPHA * x;
}

__global__ void __launch_bounds__(1024, 1)
fused_convolve(const float* __restrict__ emb,
               const float* __restrict__ weights,
               const float* __restrict__ Qw,
               const float* __restrict__ Qb,
               const float* __restrict__ Ww,
               const float* __restrict__ Wb,
               const int*   __restrict__ nb,
               const int*   __restrict__ nid_p,
               float*       __restrict__ out)
{
    // Shared memory, carved per role (max 36.9 KB, static).
    __shared__ __align__(16) unsigned char smem_raw[37376];
    __shared__ float s_misc[12];

    const int bid = blockIdx.x;
    const int tid = threadIdx.x;
    const int nid = *nid_p;

    if (bid < NCOMPUTE) {
        // ================= COMPUTE ROLE (R10/R8 body; ws gather off chain) ======
        const int chunk = bid >> 3;   // 0..15
        const int b     = bid & 7;    // 0..7
        const int th    = tid & 63;   // h-group (float4 on Qw rows)
        const int tc    = tid >> 6;   // c-chunk 0..15 (16 c each)

        float4* part8 = (float4*)smem_raw;                    // [8][KCHUNK][64] = 32 KB
        float*  embs  = (float*)(smem_raw + 32768);           // [KCHUNK][256]  = 4 KB
        float*  ws    = (float*)(smem_raw + 36864);           // [4]
        int*    nbs   = (int*)  (smem_raw + 36880);           // [4]

        const int c0  = tc * 16;
        const float4* Qw4 = (const float4*)Qw;

        // Prefetch first 4 Qw vectors (independent of nb/emb prologue)
        float4 q0 = __ldg(&Qw4[(c0 + 0) * 64 + th]);
        float4 q1 = __ldg(&Qw4[(c0 + 1) * 64 + th]);
        float4 q2 = __ldg(&Qw4[(c0 + 2) * 64 + th]);
        float4 q3 = __ldg(&Qw4[(c0 + 3) * 64 + th]);

        if (tid < KCHUNK) {
            nbs[tid] = nb[chunk * KCHUNK + tid];
        }
        __syncthreads();   // barrier gated only on nbs (4B loads), not weights

        // weights gather issued here, consumed only after the main loop ->
        // its ~600cyc scattered-DRAM latency hides behind the loop.
        float wreg = 0.0f;
        if (tid >= 32 && tid < 32 + KCHUNK) {
            wreg = weights[(size_t)nbs[tid - 32] * NDIM + nid];
        }

        if (tid < 256) {
            int r = tid >> 6, col = tid & 63;
            ((float4*)(embs + r * CDIM))[col] =
                ((const float4*)(emb + ((size_t)b * NDIM + nbs[r]) * CDIM))[col];
        }
        __syncthreads();

        float4 a0 = make_float4(0.f,0.f,0.f,0.f);
        float4 a1 = make_float4(0.f,0.f,0.f,0.f);
        float4 a2 = make_float4(0.f,0.f,0.f,0.f);
        float4 a3 = make_float4(0.f,0.f,0.f,0.f);

        {
            float e0, e1, e2, e3;
            #define K1_FMA(Q, CI)                                                       \
                e0 = embs[0*CDIM + (CI)]; e1 = embs[1*CDIM + (CI)];                     \
                e2 = embs[2*CDIM + (CI)]; e3 = embs[3*CDIM + (CI)];                     \
                a0.x = fmaf(e0,(Q).x,a0.x); a0.y = fmaf(e0,(Q).y,a0.y);                 \
                a0.z = fmaf(e0,(Q).z,a0.z); a0.w = fmaf(e0,(Q).w,a0.w);                 \
                a1.x = fmaf(e1,(Q).x,a1.x); a1.y = fmaf(e1,(Q).y,a1.y);                 \
                a1.z = fmaf(e1,(Q).z,a1.z); a1.w = fmaf(e1,(Q).w,a1.w);                 \
                a2.x = fmaf(e2,(Q).x,a2.x); a2.y = fmaf(e2,(Q).y,a2.y);                 \
                a2.z = fmaf(e2,(Q).z,a2.z); a2.w = fmaf(e2,(Q).w,a2.w);                 \
                a3.x = fmaf(e3,(Q).x,a3.x); a3.y = fmaf(e3,(Q).y,a3.y);                 \
                a3.z = fmaf(e3,(Q).z,a3.z); a3.w = fmaf(e3,(Q).w,a3.w)

            K1_FMA(q0, c0 + 0);
            K1_FMA(q1, c0 + 1);
            K1_FMA(q2, c0 + 2);
            K1_FMA(q3, c0 + 3);

            #pragma unroll
            for (int i = 4; i < 16; i++) {
                float4 q = __ldg(&Qw4[(c0 + i) * 64 + th]);
                K1_FMA(q, c0 + i);
            }
            #undef K1_FMA
        }

        // ws becomes visible at the first epilogue barrier below.
        if (tid >= 32 && tid < 32 + KCHUNK) {
            ws[tid - 32] = wreg;
        }

        // Two-round c-chunk combine (16 chunks through the 8-slot buffer)
        #define P8(s,k,h) part8[((s) * KCHUNK + (k)) * 64 + (h)]
        if (tc >= 8) {
            P8(tc-8,0,th) = a0; P8(tc-8,1,th) = a1;
            P8(tc-8,2,th) = a2; P8(tc-8,3,th) = a3;
        }
        __syncthreads();
        if (tc < 8) {
            float4 p;
            p = P8(tc,0,th); a0.x += p.x; a0.y += p.y; a0.z += p.z; a0.w += p.w;
            p = P8(tc,1,th); a1.x += p.x; a1.y += p.y; a1.z += p.z; a1.w += p.w;
            p = P8(tc,2,th); a2.x += p.x; a2.y += p.y; a2.z += p.z; a2.w += p.w;
            p = P8(tc,3,th); a3.x += p.x; a3.y += p.y; a3.z += p.z; a3.w += p.w;
        }
        __syncthreads();
        if (tc < 8) {
            P8(tc,0,th) = a0; P8(tc,1,th) = a1;
            P8(tc,2,th) = a2; P8(tc,3,th) = a3;
        }
        __syncthreads();

        if (tid < 256) {
            int k = tid >> 6, h = tid & 63;
            float4 s = P8(0,k,h);
            #pragma unroll
            for (int i = 1; i < 8; i++) {
                float4 p = P8(i,k,h);
                s.x += p.x; s.y += p.y; s.z += p.z; s.w += p.w;
            }
            float4 qb = ((const float4*)Qb)[h];
            float  w  = ws[k];
            float4 r;
            r.x = leaky(s.x + qb.x) * w;
            r.y = leaky(s.y + qb.y) * w;
            r.z = leaky(s.z + qb.z) * w;
            r.w = leaky(s.w + qb.w) * w;
            P8(0,k,h) = r;
        }
        __syncthreads();

        if (tid < 64) {
            float4 s0 = P8(0,0,tid), s1 = P8(0,1,tid);
            float4 s2 = P8(0,2,tid), s3 = P8(0,3,tid);
            float4 s;
            s.x = s0.x + s1.x + s2.x + s3.x;
            s.y = s0.y + s1.y + s2.y + s3.y;
            s.z = s0.z + s1.z + s2.z + s3.z;
            s.w = s0.w + s1.w + s2.w + s3.w;
            ((float4*)(g_partial + ((size_t)b * NCHUNKS + chunk) * HDIM))[tid] = s;
        }
        #undef P8
        if (tid == 0) {
            g_wsum[b * NCHUNKS + chunk] = ws[0] + ws[1] + ws[2] + ws[3];
        }
        __threadfence();
        __syncthreads();
        if (tid == 0) atomicAdd(&g_done, 1);

    } else {
        // ================= GEMV ROLE: gate-split GEMV =================
        const int ob = bid - NCOMPUTE;   // 0..7, o-tile of 32

        float*  cs_s = (float*)smem_raw;                       // [8][CS_PAD] = 16.5 KB
        float4* red  = (float4*)(smem_raw + 8 * CS_PAD * 4);   // [16][64]    = 16 KB
        float*  sq   = (float*)(smem_raw + 8 * CS_PAD * 4 + 16384);  // [64]
        float*  dn   = (float*)(smem_raw + 8 * CS_PAD * 4 + 16640);  // [8]
        int*    s_fl = (int*)  (smem_raw + 8 * CS_PAD * 4 + 16672);

        // Pre-gate: node embeddings (independent of compute blocks)
        if (tid < 512) {
            int bn = tid >> 6, col = tid & 63;
            float4 v = *(const float4*)(emb + ((size_t)(bn * NDIM + nid)) * CDIM + col * 4);
            *(float4*)(cs_s + bn * CS_PAD + col * 4) = v;
        }
        __syncthreads();   // first concat half visible

        const int og = tid & 7;
        const int bb = (tid >> 3) & 7;
        const int cq = tid >> 6;
        const float4* Ww4 = (const float4*)Ww;
        const float*  e   = cs_s + bb * CS_PAD;

        float4 acc = make_float4(0.f,0.f,0.f,0.f);
        if (cq < 8) {
            // Pre-gate GEMV half: c in [0,256) uses only node embeddings.
            #pragma unroll 8
            for (int c = cq * 32; c < cq * 32 + 32; c++) {
                float  ev = e[c];
                float4 q  = __ldg(&Ww4[c * 64 + ob * 8 + og]);
                acc.x = fmaf(ev, q.x, acc.x);
                acc.y = fmaf(ev, q.y, acc.y);
                acc.z = fmaf(ev, q.z, acc.z);
                acc.w = fmaf(ev, q.w, acc.w);
            }
            red[cq * 64 + bb * 8 + og] = acc;
        } else if (bb == 0) {
            // Prime this block's post-half Ww lines into L1 while compute runs.
            // z is 0 at runtime (nid >= 0) but opaque to the compiler.
            const float z = (float)(nid >> 31);
            #pragma unroll 8
            for (int c = cq * 32; c < cq * 32 + 32; c++) {
                float4 q = __ldg(&Ww4[c * 64 + ob * 8 + og]);
                acc.x = fmaf(z, q.x, acc.x);
                acc.y = fmaf(z, q.y, acc.y);
                acc.z = fmaf(z, q.z, acc.z);
                acc.w = fmaf(z, q.w, acc.w);
            }
        }

        // Gate on compute completion
        if (tid == 0) {
            while (atomicAdd(&g_done, 0) < NCOMPUTE) __nanosleep(64);
        }
        __syncthreads();
        __threadfence();

        // Phase A remainder: reduce 16 chunk partials + denoms (cross-SM -> __ldcg)
        float s0 = 0.f, s1 = 0.f;
        {
            const int b0 = tid >> 8, h0 = tid & 255;
            const int b1 = b0 + 4;
            const float* gp0 = g_partial + ((size_t)b0 * NCHUNKS) * HDIM + h0;
            const float* gp1 = g_partial + ((size_t)b1 * NCHUNKS) * HDIM + h0;
            #pragma unroll
            for (int ch = 0; ch < NCHUNKS; ch++) {
                s0 += __ldcg(gp0 + ch * HDIM);
                s1 += __ldcg(gp1 + ch * HDIM);
            }
        }
        if (tid >= 512 && tid < 512 + BDIM) {
            const int bn = tid - 512;
            float d = 0.0f;
            #pragma unroll
            for (int i = 0; i < NCHUNKS; i++) d += __ldcg(&g_wsum[bn * NCHUNKS + i]);
            dn[bn] = d + EPS;
        }
        __syncthreads();
        {
            const int b0 = tid >> 8, h0 = tid & 255;
            const int b1 = b0 + 4;
            cs_s[b0 * CS_PAD + CDIM + h0] = s0 / dn[b0];
            cs_s[b1 * CS_PAD + CDIM + h0] = s1 / dn[b1];
        }
        __syncthreads();

        // Post-gate GEMV half: c in [256,512). Ww lines are L1-hot (primed).
        if (cq >= 8) {
            #pragma unroll 8
            for (int c = cq * 32; c < cq * 32 + 32; c++) {
                float  ev = e[c];
                float4 q  = __ldg(&Ww4[c * 64 + ob * 8 + og]);
                acc.x = fmaf(ev, q.x, acc.x);
                acc.y = fmaf(ev, q.y, acc.y);
                acc.z = fmaf(ev, q.z, acc.z);
                acc.w = fmaf(ev, q.w, acc.w);
            }
            red[cq * 64 + bb * 8 + og] = acc;
        }
        __syncthreads();

        if (tid < 64) {
            const int b2 = tid >> 3, og2 = tid & 7;
            float4 s = red[tid];
            #pragma unroll
            for (int i = 1; i < 16; i++) {
                float4 rr = red[i * 64 + tid];
                s.x += rr.x; s.y += rr.y; s.z += rr.z; s.w += rr.w;
            }
            float4 wb = ((const float4*)Wb)[ob * 8 + og2];
            float4 v;
            v.x = leaky(s.x + wb.x);
            v.y = leaky(s.y + wb.y);
            v.z = leaky(s.z + wb.z);
            v.w = leaky(s.w + wb.w);
            *(float4*)(g_hidden + (size_t)b2 * ODIM + ob * 32 + og2 * 4) = v;
            sq[tid] = v.x*v.x + v.y*v.y + v.z*v.z + v.w*v.w;
        }
        __syncthreads();
        if (tid < 8) {
            float t = 0.f;
            #pragma unroll
            for (int i = 0; i < 8; i++) t += sq[tid * 8 + i];
            g_ssq[tid * NGEMV + ob] = t;
        }
        __threadfence();
        __syncthreads();
        if (tid == 0) *s_fl = (atomicAdd(&g_arrive, 1) == NGEMV - 1);
        __syncthreads();

        if (*s_fl) {
            // Last-arriving gemv block: normalize + store + reset counters.
            __threadfence();
            if (tid < 8) {
                float t = 0.f;
                #pragma unroll
                for (int i = 0; i < 8; i++) t += __ldcg(&g_ssq[tid * NGEMV + i]);
                s_misc[tid] = 1.0f / (sqrtf(t) + EPS);
            }
            __syncthreads();
            if (tid < 512) {
                int bn = tid >> 6, o4 = tid & 63;
                float4 v = __ldcg(((const float4*)(g_hidden + (size_t)bn * ODIM)) + o4);
                float iv = s_misc[bn];
                v.x *= iv; v.y *= iv; v.z *= iv; v.w *= iv;
                *(float4*)(out + (size_t)bn * ODIM + o4 * 4) = v;
            }
            if (tid == 0) { g_done = 0; g_arrive = 0; }
        }
    }
}

extern "C" void kernel_launch(void* const* d_in, const int* in_sizes, int n_in,
                              void* d_out, int out_size)
{
    (void)in_sizes; (void)n_in; (void)out_size;
    const float* emb     = (const float*)d_in[0];
    const float* weights = (const float*)d_in[1];
    const float* Qw      = (const float*)d_in[2];
    const float* Qb      = (const float*)d_in[3];
    const float* Ww      = (const float*)d_in[4];
    const float* Wb      = (const float*)d_in[5];
    const int*   nb      = (const int*)d_in[6];
    const int*   nid     = (const int*)d_in[7];
    float*       out     = (float*)d_out;

    fused_convolve<<<NCOMPUTE + NGEMV, 1024>>>(emb, weights, Qw, Qb, Ww, Wb, nb, nid, out);
}

// round 14
// speedup vs baseline: 1.2467x; 1.0019x over previous
#include <cuda_runtime.h>
#include <cuda_bf16.h>
#include <math.h>

// Problem shapes (fixed by the dataset)
#define BDIM 8
#define NDIM 8192
#define CDIM 256
#define HDIM 256
#define ODIM 256
#define KDIM 64
#define KCHUNK 4
#define NCHUNKS (KDIM / KCHUNK)   // 16
#define NCOMPUTE (NCHUNKS * BDIM) // 128 compute blocks
#define NGEMV 8                   // gemv blocks (o-tiles of 32)
#define CONC (CDIM + HDIM)        // 512
#define CS_PAD 516                // padded concat row (conflict-free bb-split)
#define LEAKY_ALPHA 0.3f
#define EPS 1e-6f

// Global scratch / sync (no allocation)
__device__ float g_partial[BDIM * NCHUNKS * HDIM];  // per-(b,chunk) weighted hidden sums
__device__ float g_wsum[BDIM * NCHUNKS];            // per-(b,chunk) neighbor-weight sums
__device__ float g_hidden[BDIM * ODIM];             // pre-norm hidden
__device__ float g_ssq[BDIM * NGEMV];               // per-(b, o-block) sum of squares
__device__ int   g_done   = 0;                      // compute completion counter
__device__ int   g_arrive = 0;                      // gemv arrival counter

__device__ __forceinline__ float leaky(float x) {
    return x >= 0.0f ? x : LEAKY_ALPHA * x;
}

__global__ void __launch_bounds__(512, 1)
fused_convolve(const float* __restrict__ emb,
               const float* __restrict__ weights,
               const float* __restrict__ Qw,
               const float* __restrict__ Qb,
               const float* __restrict__ Ww,
               const float* __restrict__ Wb,
               const int*   __restrict__ nb,
               const int*   __restrict__ nid_p,
               float*       __restrict__ out)
{
    // Shared memory, carved per role (compute: 36.9 KB; gemv: ~25 KB).
    __shared__ __align__(16) unsigned char smem_raw[37376];
    __shared__ float s_misc[12];

    const int bid = blockIdx.x;
    const int tid = threadIdx.x;
    const int nid = *nid_p;

    if (bid < NCOMPUTE) {
        // ========= COMPUTE ROLE: 512 thr, 8-deep register prefetch queue =========
        // thread = (th: h-group of 4) x (tc: c-chunk of 32, 0..7)
        // Each thread: 32 iters of [1 LDG.128 (8 ahead) -> 16 FFMA over 4 neighbors]
        const int chunk = bid >> 3;   // 0..15
        const int b     = bid & 7;    // 0..7
        const int th    = tid & 63;   // h-group (float4 column of Qw)
        const int tc    = tid >> 6;   // c-chunk 0..7 (32 c each)

        float4* part8 = (float4*)smem_raw;            // [8][KCHUNK][64] = 32 KB
        float*  embs  = (float*)(smem_raw + 32768);   // [KCHUNK][256]  = 4 KB
        float*  ws    = (float*)(smem_raw + 36864);   // [4]
        int*    nbs   = (int*)  (smem_raw + 36880);   // [4]

        const int c0 = tc * 32;
        const float4* Qw4 = (const float4*)Qw;

        // Prime the 8-deep queue (independent of nb/emb prologue -> overlaps it)
        float4 q[8];
        #pragma unroll
        for (int j = 0; j < 8; j++) q[j] = __ldg(&Qw4[(c0 + j) * 64 + th]);

        if (tid < KCHUNK) {
            nbs[tid] = nb[chunk * KCHUNK + tid];
        }
        __syncthreads();   // gated only on nbs

        // weights gather off the critical chain (consumed post-loop)
        float wreg = 0.0f;
        if (tid >= 32 && tid < 32 + KCHUNK) {
            wreg = weights[(size_t)nbs[tid - 32] * NDIM + nid];
        }

        if (tid < 256) {
            int r = tid >> 6, col = tid & 63;
            ((float4*)(embs + r * CDIM))[col] =
                ((const float4*)(emb + ((size_t)b * NDIM + nbs[r]) * CDIM))[col];
        }
        __syncthreads();

        float4 a0 = make_float4(0.f,0.f,0.f,0.f);
        float4 a1 = make_float4(0.f,0.f,0.f,0.f);
        float4 a2 = make_float4(0.f,0.f,0.f,0.f);
        float4 a3 = make_float4(0.f,0.f,0.f,0.f);

        #pragma unroll
        for (int i = 0; i < 32; i++) {
            float4 qq = q[i & 7];
            if (i < 24) q[i & 7] = __ldg(&Qw4[(c0 + i + 8) * 64 + th]);
            const int c = c0 + i;
            float e0 = embs[0*CDIM + c], e1 = embs[1*CDIM + c];
            float e2 = embs[2*CDIM + c], e3 = embs[3*CDIM + c];
            a0.x = fmaf(e0,qq.x,a0.x); a0.y = fmaf(e0,qq.y,a0.y);
            a0.z = fmaf(e0,qq.z,a0.z); a0.w = fmaf(e0,qq.w,a0.w);
            a1.x = fmaf(e1,qq.x,a1.x); a1.y = fmaf(e1,qq.y,a1.y);
            a1.z = fmaf(e1,qq.z,a1.z); a1.w = fmaf(e1,qq.w,a1.w);
            a2.x = fmaf(e2,qq.x,a2.x); a2.y = fmaf(e2,qq.y,a2.y);
            a2.z = fmaf(e2,qq.z,a2.z); a2.w = fmaf(e2,qq.w,a2.w);
            a3.x = fmaf(e3,qq.x,a3.x); a3.y = fmaf(e3,qq.y,a3.y);
            a3.z = fmaf(e3,qq.z,a3.z); a3.w = fmaf(e3,qq.w,a3.w);
        }

        // ws visible at the next barrier
        if (tid >= 32 && tid < 32 + KCHUNK) {
            ws[tid - 32] = wreg;
        }

        // c-chunk combine: 8 partials, one barrier.
        #define P8(s,k,h) part8[((s) * KCHUNK + (k)) * 64 + (h)]
        P8(tc,0,th) = a0; P8(tc,1,th) = a1;
        P8(tc,2,th) = a2; P8(tc,3,th) = a3;
        __syncthreads();

        if (tid < 256) {
            int k = tid >> 6, h = tid & 63;
            float4 s = P8(0,k,h);
            #pragma unroll
            for (int i = 1; i < 8; i++) {
                float4 p = P8(i,k,h);
                s.x += p.x; s.y += p.y; s.z += p.z; s.w += p.w;
            }
            float4 qb = ((const float4*)Qb)[h];
            float  w  = ws[k];
            float4 r;
            r.x = leaky(s.x + qb.x) * w;
            r.y = leaky(s.y + qb.y) * w;
            r.z = leaky(s.z + qb.z) * w;
            r.w = leaky(s.w + qb.w) * w;
            P8(0,k,h) = r;   // safe: each (k,h) read only by its owner thread
        }
        __syncthreads();

        if (tid < 64) {
            float4 s0 = P8(0,0,tid), s1 = P8(0,1,tid);
            float4 s2 = P8(0,2,tid), s3 = P8(0,3,tid);
            float4 s;
            s.x = s0.x + s1.x + s2.x + s3.x;
            s.y = s0.y + s1.y + s2.y + s3.y;
            s.z = s0.z + s1.z + s2.z + s3.z;
            s.w = s0.w + s1.w + s2.w + s3.w;
            ((float4*)(g_partial + ((size_t)b * NCHUNKS + chunk) * HDIM))[tid] = s;
        }
        #undef P8
        if (tid == 0) {
            g_wsum[b * NCHUNKS + chunk] = ws[0] + ws[1] + ws[2] + ws[3];
        }
        __threadfence();
        __syncthreads();
        if (tid == 0) atomicAdd(&g_done, 1);

    } else {
        // ================= GEMV ROLE (512 thr, gate-split) =================
        const int ob = bid - NCOMPUTE;   // 0..7, o-tile of 32

        float*  cs_s = (float*)smem_raw;                       // [8][CS_PAD] = 16.5 KB
        float4* red  = (float4*)(smem_raw + 8 * CS_PAD * 4);   // [8][64] = 8 KB
        float*  sq   = (float*)(smem_raw + 8 * CS_PAD * 4 + 8192);   // [64]
        float*  dn   = (float*)(smem_raw + 8 * CS_PAD * 4 + 8448);   // [8]
        int*    s_fl = (int*)  (smem_raw + 8 * CS_PAD * 4 + 8480);

        // Pre-gate: node embeddings (one float4 per thread)
        {
            int bn = tid >> 6, col = tid & 63;
            float4 v = *(const float4*)(emb + ((size_t)(bn * NDIM + nid)) * CDIM + col * 4);
            *(float4*)(cs_s + bn * CS_PAD + col * 4) = v;
        }
        __syncthreads();   // first concat half visible

        const int og = tid & 7;
        const int bb = (tid >> 3) & 7;
        const int cq = tid >> 6;        // 0..7, c-chunks of 64
        const float4* Ww4 = (const float4*)Ww;
        const float*  e   = cs_s + bb * CS_PAD;

        float4 acc = make_float4(0.f,0.f,0.f,0.f);
        if (cq < 4) {
            // Pre-gate half: c in [0,256)
            #pragma unroll 8
            for (int c = cq * 64; c < cq * 64 + 64; c++) {
                float  ev = e[c];
                float4 qv = __ldg(&Ww4[c * 64 + ob * 8 + og]);
                acc.x = fmaf(ev, qv.x, acc.x);
                acc.y = fmaf(ev, qv.y, acc.y);
                acc.z = fmaf(ev, qv.z, acc.z);
                acc.w = fmaf(ev, qv.w, acc.w);
            }
            red[cq * 64 + bb * 8 + og] = acc;
        } else if (bb == 0) {
            // Prime post-half Ww lines into L1 (z == 0 at runtime, opaque)
            const float z = (float)(nid >> 31);
            #pragma unroll 8
            for (int c = cq * 64; c < cq * 64 + 64; c++) {
                float4 qv = __ldg(&Ww4[c * 64 + ob * 8 + og]);
                acc.x = fmaf(z, qv.x, acc.x);
                acc.y = fmaf(z, qv.y, acc.y);
                acc.z = fmaf(z, qv.z, acc.z);
                acc.w = fmaf(z, qv.w, acc.w);
            }
        }

        // Gate on compute completion
        if (tid == 0) {
            while (atomicAdd(&g_done, 0) < NCOMPUTE) __nanosleep(64);
        }
        __syncthreads();
        __threadfence();

        // Phase A remainder: wsum gather (float4 over h) + denoms
        float4 s4;
        {
            const int bn = tid >> 6, h4 = tid & 63;
            const float4* gp = (const float4*)(g_partial + (size_t)bn * NCHUNKS * HDIM) + h4;
            s4 = __ldcg(gp);
            #pragma unroll
            for (int ch = 1; ch < NCHUNKS; ch++) {
                float4 p = __ldcg(gp + ch * 64);
                s4.x += p.x; s4.y += p.y; s4.z += p.z; s4.w += p.w;
            }
        }
        if (tid < BDIM) {
            float d = 0.0f;
            #pragma unroll
            for (int i = 0; i < NCHUNKS; i++) d += __ldcg(&g_wsum[tid * NCHUNKS + i]);
            dn[tid] = d + EPS;
        }
        __syncthreads();
        {
            const int bn = tid >> 6, h4 = tid & 63;
            float inv = 1.0f / dn[bn];
            float4 o;
            o.x = s4.x * inv; o.y = s4.y * inv; o.z = s4.z * inv; o.w = s4.w * inv;
            *(float4*)(cs_s + bn * CS_PAD + CDIM + h4 * 4) = o;
        }
        __syncthreads();

        // Post-gate half: c in [256,512), Ww lines L1-hot
        if (cq >= 4) {
            #pragma unroll 8
            for (int c = cq * 64; c < cq * 64 + 64; c++) {
                float  ev = e[c];
                float4 qv = __ldg(&Ww4[c * 64 + ob * 8 + og]);
                acc.x = fmaf(ev, qv.x, acc.x);
                acc.y = fmaf(ev, qv.y, acc.y);
                acc.z = fmaf(ev, qv.z, acc.z);
                acc.w = fmaf(ev, qv.w, acc.w);
            }
            red[cq * 64 + bb * 8 + og] = acc;
        }
        __syncthreads();

        if (tid < 64) {
            const int b2 = tid >> 3, og2 = tid & 7;
            float4 s = red[tid];
            #pragma unroll
            for (int i = 1; i < 8; i++) {
                float4 rr = red[i * 64 + tid];
                s.x += rr.x; s.y += rr.y; s.z += rr.z; s.w += rr.w;
            }
            float4 wb = ((const float4*)Wb)[ob * 8 + og2];
            float4 v;
            v.x = leaky(s.x + wb.x);
            v.y = leaky(s.y + wb.y);
            v.z = leaky(s.z + wb.z);
            v.w = leaky(s.w + wb.w);
            *(float4*)(g_hidden + (size_t)b2 * ODIM + ob * 32 + og2 * 4) = v;
            sq[tid] = v.x*v.x + v.y*v.y + v.z*v.z + v.w*v.w;
        }
        __syncthreads();
        if (tid < 8) {
            float t = 0.f;
            #pragma unroll
            for (int i = 0; i < 8; i++) t += sq[tid * 8 + i];
            g_ssq[tid * NGEMV + ob] = t;
        }
        __threadfence();
        __syncthreads();
        if (tid == 0) *s_fl = (atomicAdd(&g_arrive, 1) == NGEMV - 1);
        __syncthreads();

        if (*s_fl) {
            // Last-arriving gemv block: normalize + store + reset counters.
            __threadfence();
            if (tid < 8) {
                float t = 0.f;
                #pragma unroll
                for (int i = 0; i < 8; i++) t += __ldcg(&g_ssq[tid * NGEMV + i]);
                s_misc[tid] = 1.0f / (sqrtf(t) + EPS);
            }
            __syncthreads();
            {
                int bn = tid >> 6, o4 = tid & 63;
                float4 v = __ldcg(((const float4*)(g_hidden + (size_t)bn * ODIM)) + o4);
                float iv = s_misc[bn];
                v.x *= iv; v.y *= iv; v.z *= iv; v.w *= iv;
                *(float4*)(out + (size_t)bn * ODIM + o4 * 4) = v;
            }
            if (tid == 0) { g_done = 0; g_arrive = 0; }
        }
    }
}

extern "C" void kernel_launch(void* const* d_in, const int* in_sizes, int n_in,
                              void* d_out, int out_size)
{
    (void)in_sizes; (void)n_in; (void)out_size;
    const float* emb     = (const float*)d_in[0];
    const float* weights = (const float*)d_in[1];
    const float* Qw      = (const float*)d_in[2];
    const float* Qb      = (const float*)d_in[3];
    const float* Ww      = (const float*)d_in[4];
    const float* Wb      = (const float*)d_in[5];
    const int*   nb      = (const int*)d_in[6];
    const int*   nid     = (const int*)d_in[7];
    float*       out     = (float*)d_out;

    fused_convolve<<<NCOMPUTE + NGEMV, 512>>>(emb, weights, Qw, Qb, Ww, Wb, nb, nid, out);
}

// round 16
// speedup vs baseline: 1.4406x; 1.1555x over previous
#include <cuda_runtime.h>
#include <cuda_bf16.h>
#include <math.h>

// Problem shapes (fixed by the dataset)
#define BDIM 8
#define NDIM 8192
#define CDIM 256
#define HDIM 256
#define ODIM 256
#define KDIM 64
#define KCHUNK 4
#define NCHUNKS (KDIM / KCHUNK)   // 16
#define NCOMPUTE (NCHUNKS * BDIM) // 128 compute blocks
#define NGEMV 16                  // gemv blocks (o-tiles of 16)
#define CONC (CDIM + HDIM)        // 512
#define CS_PAD 516                // padded concat row (conflict-free bb-split)
#define LEAKY_ALPHA 0.3f
#define EPS 1e-6f

// Global scratch / sync (no allocation)
__device__ float g_partial[BDIM * NCHUNKS * HDIM];  // per-(b,chunk) weighted hidden sums
__device__ float g_wsum[BDIM * NCHUNKS];            // per-(b,chunk) neighbor-weight sums
__device__ float g_hidden[BDIM * ODIM];             // pre-norm hidden
__device__ float g_ssq[BDIM * NGEMV];               // per-(b, o-block) sum of squares
__device__ int   g_done   = 0;                      // compute completion counter
__device__ int   g_arrive = 0;                      // gemv arrival counter

__device__ __forceinline__ float leaky(float x) {
    return x >= 0.0f ? x : LEAKY_ALPHA * x;
}

__global__ void __launch_bounds__(512, 1)
fused_convolve(const float* __restrict__ emb,
               const float* __restrict__ weights,
               const float* __restrict__ Qw,
               const float* __restrict__ Qb,
               const float* __restrict__ Ww,
               const float* __restrict__ Wb,
               const int*   __restrict__ nb,
               const int*   __restrict__ nid_p,
               float*       __restrict__ out)
{
    // Shared memory, carved per role (compute: 36.9 KB; gemv: ~25 KB).
    __shared__ __align__(16) unsigned char smem_raw[37376];
    __shared__ float s_misc[12];

    const int bid = blockIdx.x;
    const int tid = threadIdx.x;
    const int nid = *nid_p;

    if (bid < NCOMPUTE) {
        // ========= COMPUTE ROLE: 512 thr, 8-deep register prefetch queue =========
        const int chunk = bid >> 3;   // 0..15
        const int b     = bid & 7;    // 0..7
        const int th    = tid & 63;   // h-group (float4 column of Qw)
        const int tc    = tid >> 6;   // c-chunk 0..7 (32 c each)

        float4* part8 = (float4*)smem_raw;            // [8][KCHUNK][64] = 32 KB
        float*  embs  = (float*)(smem_raw + 32768);   // [KCHUNK][256]  = 4 KB
        float*  ws    = (float*)(smem_raw + 36864);   // [4]
        int*    nbs   = (int*)  (smem_raw + 36880);   // [4]

        const int c0 = tc * 32;
        const float4* Qw4 = (const float4*)Qw;

        // Prime the 8-deep queue (independent of nb/emb prologue -> overlaps it)
        float4 q[8];
        #pragma unroll
        for (int j = 0; j < 8; j++) q[j] = __ldg(&Qw4[(c0 + j) * 64 + th]);

        if (tid < KCHUNK) {
            nbs[tid] = nb[chunk * KCHUNK + tid];
        }
        __syncthreads();   // gated only on nbs

        // weights gather off the critical chain (consumed post-loop)
        float wreg = 0.0f;
        if (tid >= 32 && tid < 32 + KCHUNK) {
            wreg = weights[(size_t)nbs[tid - 32] * NDIM + nid];
        }

        if (tid < 256) {
            int r = tid >> 6, col = tid & 63;
            ((float4*)(embs + r * CDIM))[col] =
                ((const float4*)(emb + ((size_t)b * NDIM + nbs[r]) * CDIM))[col];
        }
        __syncthreads();

        float4 a0 = make_float4(0.f,0.f,0.f,0.f);
        float4 a1 = make_float4(0.f,0.f,0.f,0.f);
        float4 a2 = make_float4(0.f,0.f,0.f,0.f);
        float4 a3 = make_float4(0.f,0.f,0.f,0.f);

        #pragma unroll
        for (int i = 0; i < 32; i++) {
            float4 qq = q[i & 7];
            if (i < 24) q[i & 7] = __ldg(&Qw4[(c0 + i + 8) * 64 + th]);
            const int c = c0 + i;
            float e0 = embs[0*CDIM + c], e1 = embs[1*CDIM + c];
            float e2 = embs[2*CDIM + c], e3 = embs[3*CDIM + c];
            a0.x = fmaf(e0,qq.x,a0.x); a0.y = fmaf(e0,qq.y,a0.y);
            a0.z = fmaf(e0,qq.z,a0.z); a0.w = fmaf(e0,qq.w,a0.w);
            a1.x = fmaf(e1,qq.x,a1.x); a1.y = fmaf(e1,qq.y,a1.y);
            a1.z = fmaf(e1,qq.z,a1.z); a1.w = fmaf(e1,qq.w,a1.w);
            a2.x = fmaf(e2,qq.x,a2.x); a2.y = fmaf(e2,qq.y,a2.y);
            a2.z = fmaf(e2,qq.z,a2.z); a2.w = fmaf(e2,qq.w,a2.w);
            a3.x = fmaf(e3,qq.x,a3.x); a3.y = fmaf(e3,qq.y,a3.y);
            a3.z = fmaf(e3,qq.z,a3.z); a3.w = fmaf(e3,qq.w,a3.w);
        }

        // ws visible at the next barrier
        if (tid >= 32 && tid < 32 + KCHUNK) {
            ws[tid - 32] = wreg;
        }

        // c-chunk combine: 8 partials, one barrier.
        #define P8(s,k,h) part8[((s) * KCHUNK + (k)) * 64 + (h)]
        P8(tc,0,th) = a0; P8(tc,1,th) = a1;
        P8(tc,2,th) = a2; P8(tc,3,th) = a3;
        __syncthreads();

        if (tid < 256) {
            int k = tid >> 6, h = tid & 63;
            float4 s = P8(0,k,h);
            #pragma unroll
            for (int i = 1; i < 8; i++) {
                float4 p = P8(i,k,h);
                s.x += p.x; s.y += p.y; s.z += p.z; s.w += p.w;
            }
            float4 qb = ((const float4*)Qb)[h];
            float  w  = ws[k];
            float4 r;
            r.x = leaky(s.x + qb.x) * w;
            r.y = leaky(s.y + qb.y) * w;
            r.z = leaky(s.z + qb.z) * w;
            r.w = leaky(s.w + qb.w) * w;
            P8(0,k,h) = r;   // safe: each (k,h) read only by its owner thread
        }
        __syncthreads();

        if (tid < 64) {
            float4 s0 = P8(0,0,tid), s1 = P8(0,1,tid);
            float4 s2 = P8(0,2,tid), s3 = P8(0,3,tid);
            float4 s;
            s.x = s0.x + s1.x + s2.x + s3.x;
            s.y = s0.y + s1.y + s2.y + s3.y;
            s.z = s0.z + s1.z + s2.z + s3.z;
            s.w = s0.w + s1.w + s2.w + s3.w;
            ((float4*)(g_partial + ((size_t)b * NCHUNKS + chunk) * HDIM))[tid] = s;
        }
        #undef P8
        if (tid == 0) {
            g_wsum[b * NCHUNKS + chunk] = ws[0] + ws[1] + ws[2] + ws[3];
        }
        __threadfence();
        __syncthreads();
        if (tid == 0) atomicAdd(&g_done, 1);

    } else {
        // ========= GEMV ROLE: 16 blocks, o-tile of 16, gate-split =========
        const int ob = bid - NCOMPUTE;   // 0..15, o-tile of 16 outputs (4 float4)

        float*  cs_s = (float*)smem_raw;                       // [8][CS_PAD] = 16.5 KB
        float4* red  = (float4*)(smem_raw + 8 * CS_PAD * 4);   // [16][32] = 8 KB
        float*  sq   = (float*)(smem_raw + 8 * CS_PAD * 4 + 8192);   // [32]
        float*  dn   = (float*)(smem_raw + 8 * CS_PAD * 4 + 8320);   // [8]
        int*    s_fl = (int*)  (smem_raw + 8 * CS_PAD * 4 + 8352);

        // Pre-gate: node embeddings (one float4 per thread)
        {
            int bn = tid >> 6, col = tid & 63;
            float4 v = *(const float4*)(emb + ((size_t)(bn * NDIM + nid)) * CDIM + col * 4);
            *(float4*)(cs_s + bn * CS_PAD + col * 4) = v;
        }
        __syncthreads();   // first concat half visible

        const int og = tid & 3;          // float4 within the 16-o slice
        const int bb = (tid >> 2) & 7;   // batch
        const int cq = tid >> 5;         // 0..15, c-chunks of 32
        const float4* Ww4 = (const float4*)Ww;
        const float*  e   = cs_s + bb * CS_PAD;

        float4 acc = make_float4(0.f,0.f,0.f,0.f);
        if (cq < 8) {
            // Pre-gate half: c in [0,256)
            #pragma unroll 8
            for (int c = cq * 32; c < cq * 32 + 32; c++) {
                float  ev = e[c];
                float4 qv = __ldg(&Ww4[c * 64 + ob * 4 + og]);
                acc.x = fmaf(ev, qv.x, acc.x);
                acc.y = fmaf(ev, qv.y, acc.y);
                acc.z = fmaf(ev, qv.z, acc.z);
                acc.w = fmaf(ev, qv.w, acc.w);
            }
            red[cq * 32 + bb * 4 + og] = acc;
        } else if (bb == 0) {
            // Prime post-half Ww lines into L1 (z == 0 at runtime, opaque)
            const float z = (float)(nid >> 31);
            #pragma unroll 8
            for (int c = cq * 32; c < cq * 32 + 32; c++) {
                float4 qv = __ldg(&Ww4[c * 64 + ob * 4 + og]);
                acc.x = fmaf(z, qv.x, acc.x);
                acc.y = fmaf(z, qv.y, acc.y);
                acc.z = fmaf(z, qv.z, acc.z);
                acc.w = fmaf(z, qv.w, acc.w);
            }
        }

        // Gate on compute completion
        if (tid == 0) {
            while (atomicAdd(&g_done, 0) < NCOMPUTE) __nanosleep(64);
        }
        __syncthreads();
        __threadfence();

        // Phase A remainder: wsum gather (float4 over h) + denoms
        float4 s4;
        {
            const int bn = tid >> 6, h4 = tid & 63;
            const float4* gp = (const float4*)(g_partial + (size_t)bn * NCHUNKS * HDIM) + h4;
            s4 = __ldcg(gp);
            #pragma unroll
            for (int ch = 1; ch < NCHUNKS; ch++) {
                float4 p = __ldcg(gp + ch * 64);
                s4.x += p.x; s4.y += p.y; s4.z += p.z; s4.w += p.w;
            }
        }
        if (tid < BDIM) {
            float d = 0.0f;
            #pragma unroll
            for (int i = 0; i < NCHUNKS; i++) d += __ldcg(&g_wsum[tid * NCHUNKS + i]);
            dn[tid] = d + EPS;
        }
        __syncthreads();
        {
            const int bn = tid >> 6, h4 = tid & 63;
            float inv = 1.0f / dn[bn];
            float4 o;
            o.x = s4.x * inv; o.y = s4.y * inv; o.z = s4.z * inv; o.w = s4.w * inv;
            *(float4*)(cs_s + bn * CS_PAD + CDIM + h4 * 4) = o;
        }
        __syncthreads();

        // Post-gate half: c in [256,512), Ww lines L1-hot
        if (cq >= 8) {
            #pragma unroll 8
            for (int c = cq * 32; c < cq * 32 + 32; c++) {
                float  ev = e[c];
                float4 qv = __ldg(&Ww4[c * 64 + ob * 4 + og]);
                acc.x = fmaf(ev, qv.x, acc.x);
                acc.y = fmaf(ev, qv.y, acc.y);
                acc.z = fmaf(ev, qv.z, acc.z);
                acc.w = fmaf(ev, qv.w, acc.w);
            }
            red[cq * 32 + bb * 4 + og] = acc;
        }
        __syncthreads();

        if (tid < 32) {
            const int b2 = tid >> 2, og2 = tid & 3;
            float4 s = red[tid];
            #pragma unroll
            for (int i = 1; i < 16; i++) {
                float4 rr = red[i * 32 + tid];
                s.x += rr.x; s.y += rr.y; s.z += rr.z; s.w += rr.w;
            }
            float4 wb = ((const float4*)Wb)[ob * 4 + og2];
            float4 v;
            v.x = leaky(s.x + wb.x);
            v.y = leaky(s.y + wb.y);
            v.z = leaky(s.z + wb.z);
            v.w = leaky(s.w + wb.w);
            *(float4*)(g_hidden + (size_t)b2 * ODIM + ob * 16 + og2 * 4) = v;
            sq[tid] = v.x*v.x + v.y*v.y + v.z*v.z + v.w*v.w;
        }
        __syncthreads();
        if (tid < 8) {
            float t = 0.f;
            #pragma unroll
            for (int i = 0; i < 4; i++) t += sq[tid * 4 + i];
            g_ssq[tid * NGEMV + ob] = t;
        }
        __threadfence();
        __syncthreads();
        if (tid == 0) *s_fl = (atomicAdd(&g_arrive, 1) == NGEMV - 1);
        __syncthreads();

        if (*s_fl) {
            // Last-arriving gemv block: normalize + store + reset counters.
            __threadfence();
            if (tid < 8) {
                float t = 0.f;
                #pragma unroll
                for (int i = 0; i < NGEMV; i++) t += __ldcg(&g_ssq[tid * NGEMV + i]);
                s_misc[tid] = 1.0f / (sqrtf(t) + EPS);
            }
            __syncthreads();
            {
                int bn = tid >> 6, o4 = tid & 63;
                float4 v = __ldcg(((const float4*)(g_hidden + (size_t)bn * ODIM)) + o4);
                float iv = s_misc[bn];
                v.x *= iv; v.y *= iv; v.z *= iv; v.w *= iv;
                *(float4*)(out + (size_t)bn * ODIM + o4 * 4) = v;
            }
            if (tid == 0) { g_done = 0; g_arrive = 0; }
        }
    }
}

extern "C" void kernel_launch(void* const* d_in, const int* in_sizes, int n_in,
                              void* d_out, int out_size)
{
    (void)in_sizes; (void)n_in; (void)out_size;
    const float* emb     = (const float*)d_in[0];
    const float* weights = (const float*)d_in[1];
    const float* Qw      = (const float*)d_in[2];
    const float* Qb      = (const float*)d_in[3];
    const float* Ww      = (const float*)d_in[4];
    const float* Wb      = (const float*)d_in[5];
    const int*   nb      = (const int*)d_in[6];
    const int*   nid     = (const int*)d_in[7];
    float*       out     = (float*)d_out;

    fused_convolve<<<NCOMPUTE + NGEMV, 512>>>(emb, weights, Qw, Qb, Ww, Wb, nb, nid, out);
}